// round 9
// baseline (speedup 1.0000x reference)
#include <cuda_runtime.h>
#include <cuda_bf16.h>
#include <cstdint>

#define GNUM   2048
#define NPG    57
#define NNODES (GNUM*NPG)      // 116736
#define EPG    160
#define NEDGES (GNUM*EPG)      // 327680
#define HID    256
#define NLAY   5
#define NEF    (GNUM*80)       // 163840

// ---------------- scratch (static __device__ arrays; no allocs) ----------------
// h and t2' live as bf16 hi/lo planes (GEMM-A operands); raw intermediates fp32.
__device__ unsigned short d_hhi [(size_t)NNODES*HID];
__device__ unsigned short d_hlo [(size_t)NNODES*HID];
__device__ unsigned short d_t2hi[(size_t)NNODES*HID];
__device__ unsigned short d_t2lo[(size_t)NNODES*HID];
__device__ float d_t2  [(size_t)NNODES*HID];   // raw h@U1top
__device__ float d_agg [(size_t)NNODES*HID];   // S accumulator (fp32 atomics)
__device__ float d_P   [(size_t)NNODES*HID];
__device__ float d_Q   [(size_t)NNODES*HID];
__device__ float d_invdeg [NNODES];
__device__ float d_b2f    [NNODES];
__device__ float d_bnscale[NLAY*HID];
__device__ float d_bnshift[NLAY*HID];
__device__ float d_wcf [(size_t)256*256];
__device__ float d_cvec[(size_t)NLAY*HID];
// transposed, bf16-split weights: [256 out, K] K-major, hi + lo
__device__ unsigned short d_bhi_m1[(size_t)NLAY*256*512];
__device__ unsigned short d_blo_m1[(size_t)NLAY*256*512];
__device__ unsigned short d_bhi_u1[(size_t)NLAY*256*512];
__device__ unsigned short d_blo_u1[(size_t)NLAY*256*512];
__device__ unsigned short d_bhi_u2[(size_t)NLAY*256*256];
__device__ unsigned short d_blo_u2[(size_t)NLAY*256*256];
__device__ unsigned short d_bhi_c [(size_t)NLAY*256*256];
__device__ unsigned short d_blo_c [(size_t)NLAY*256*256];
__device__ unsigned short d_bhi_r [(size_t)256*512];
__device__ unsigned short d_blo_r [(size_t)256*512];

// ---------------- PTX helpers ----------------
__device__ __forceinline__ uint32_t smem_u32(const void* p) {
    uint32_t a;
    asm("{ .reg .u64 t; cvta.to.shared.u64 t, %1; cvt.u32.u64 %0, t; }" : "=r"(a) : "l"(p));
    return a;
}
__device__ __forceinline__ void cp_async16(uint32_t smem, const void* g) {
    asm volatile("cp.async.cg.shared.global [%0], [%1], 16;" :: "r"(smem), "l"(g) : "memory");
}
#define CP_COMMIT() asm volatile("cp.async.commit_group;" ::: "memory")
#define CP_WAIT1()  asm volatile("cp.async.wait_group 1;" ::: "memory")
#define CP_WAIT0()  asm volatile("cp.async.wait_group 0;" ::: "memory")

__device__ __forceinline__ void mma_bf16(float* d, const uint32_t* a, const uint32_t* b) {
    asm volatile(
        "mma.sync.aligned.m16n8k16.row.col.f32.bf16.bf16.f32 "
        "{%0,%1,%2,%3}, {%4,%5,%6,%7}, {%8,%9}, {%0,%1,%2,%3};"
        : "+f"(d[0]), "+f"(d[1]), "+f"(d[2]), "+f"(d[3])
        : "r"(a[0]), "r"(a[1]), "r"(a[2]), "r"(a[3]), "r"(b[0]), "r"(b[1]));
}
__device__ __forceinline__ void red_add_v4(float* p, float a, float b, float c, float d) {
    asm volatile("red.global.add.v4.f32 [%0], {%1, %2, %3, %4};"
                 :: "l"(p), "f"(a), "f"(b), "f"(c), "f"(d) : "memory");
}
__device__ __forceinline__ void split_bf16x2(float2 v, uint32_t& hi, uint32_t& lo) {
    asm("cvt.rn.bf16x2.f32 %0, %1, %2;" : "=r"(hi) : "f"(v.y), "f"(v.x));
    float hlo = __uint_as_float(hi << 16);
    float hhi = __uint_as_float(hi & 0xFFFF0000u);
    asm("cvt.rn.bf16x2.f32 %0, %1, %2;" : "=r"(lo) : "f"(v.y - hhi), "f"(v.x - hlo));
}
__device__ __forceinline__ float2 join_bf16x2(uint32_t hi, uint32_t lo) {
    float2 r;
    r.x = __uint_as_float(hi << 16)          + __uint_as_float(lo << 16);
    r.y = __uint_as_float(hi & 0xFFFF0000u)  + __uint_as_float(lo & 0xFFFF0000u);
    return r;
}

// ---------------- small helper kernels ----------------
__global__ void zero_agg_kernel() {
    size_t n4 = (size_t)NNODES*HID/4;
    float4 z = make_float4(0.f,0.f,0.f,0.f);
    for (size_t i = (size_t)blockIdx.x*blockDim.x + threadIdx.x; i < n4;
         i += (size_t)gridDim.x*blockDim.x)
        ((float4*)d_agg)[i] = z;
}
__global__ void deg_zero_kernel() {
    int i = blockIdx.x*blockDim.x + threadIdx.x;
    if (i < NNODES) d_invdeg[i] = 0.f;
}
__global__ void deg_count_kernel(const int* __restrict__ dst) {
    int e = blockIdx.x*blockDim.x + threadIdx.x;
    if (e < NEDGES) atomicAdd(&d_invdeg[dst[e]], 1.f);
}
__global__ void deg_inv_kernel() {
    int i = blockIdx.x*blockDim.x + threadIdx.x;
    if (i < NNODES) {
        float c = d_invdeg[i];
        d_invdeg[i] = 1.f / fmaxf(c, 1.f);
        d_b2f[i] = (c > 0.f) ? 1.f : 0.f;
    }
}
__global__ void bn_prep_kernel(const float* __restrict__ g, const float* __restrict__ b,
                               const float* __restrict__ m, const float* __restrict__ v) {
    int i = blockIdx.x*blockDim.x + threadIdx.x;
    if (i < NLAY*HID) {
        float sc = g[i] * rsqrtf(v[i] + 1e-5f);
        d_bnscale[i] = sc;
        d_bnshift[i] = b[i] - m[i]*sc;
    }
}
__global__ void input_gemm_kernel(const float* __restrict__ x,
                                  const float* __restrict__ w,
                                  const float* __restrict__ b) {
    int n = blockIdx.x;
    int c = threadIdx.x;
    __shared__ float xs[16];
    if (c < 16) xs[c] = x[n*16 + c];
    __syncthreads();
    float acc = b[c];
#pragma unroll
    for (int k = 0; k < 16; k++) acc = fmaf(xs[k], w[k*HID + c], acc);
    __nv_bfloat16 hb = __float2bfloat16(acc);
    __nv_bfloat16 lb = __float2bfloat16(acc - __bfloat162float(hb));
    d_hhi[(size_t)n*HID + c] = __bfloat16_as_ushort(hb);
    d_hlo[(size_t)n*HID + c] = __bfloat16_as_ushort(lb);
}
__global__ void cvec_kernel(const float* __restrict__ b2,
                            const float* __restrict__ u1,
                            float* __restrict__ outc) {
    int n = threadIdx.x;
    float s = 0.f;
    for (int k = 0; k < 256; k++)
        s = fmaf(b2[k], u1[(size_t)(256 + k)*256 + n], s);
    outc[n] = s;
}
// W [K,256] row-major -> hi/lo bf16 [256,K] row-major
template<int DSEL>
__global__ void transpose_split_kernel(const float* __restrict__ W, int layer, int K) {
    __shared__ float tile[32][33];
    unsigned short *WH, *WL;
    if      constexpr (DSEL == 0) { WH = d_bhi_m1 + (size_t)layer*256*512; WL = d_blo_m1 + (size_t)layer*256*512; }
    else if constexpr (DSEL == 2) { WH = d_bhi_u1 + (size_t)layer*256*512; WL = d_blo_u1 + (size_t)layer*256*512; }
    else if constexpr (DSEL == 3) { WH = d_bhi_u2 + (size_t)layer*256*256; WL = d_blo_u2 + (size_t)layer*256*256; }
    else if constexpr (DSEL == 5) { WH = d_bhi_c  + (size_t)layer*256*256; WL = d_blo_c  + (size_t)layer*256*256; }
    else                          { WH = d_bhi_r; WL = d_blo_r; }
    int kb = blockIdx.x*32, nb = blockIdx.y*32;
    for (int r = threadIdx.y; r < 32; r += 8)
        tile[r][threadIdx.x] = W[(size_t)(kb + r)*256 + nb + threadIdx.x];
    __syncthreads();
    for (int r = threadIdx.y; r < 32; r += 8) {
        float v = tile[threadIdx.x][r];
        __nv_bfloat16 hb = __float2bfloat16(v);
        __nv_bfloat16 lb = __float2bfloat16(v - __bfloat162float(hb));
        size_t o = (size_t)(nb + r)*K + kb + threadIdx.x;
        WH[o] = __bfloat16_as_ushort(hb);
        WL[o] = __bfloat16_as_ushort(lb);
    }
}

// edge scatter: S[dst] += relu(P[dst] + Q[src])
__global__ __launch_bounds__(256, 8)
void edge_scatter_kernel(const int* __restrict__ srcI, const int* __restrict__ dstI) {
    int e    = blockIdx.x*8 + (threadIdx.x >> 5);
    int lane = threadIdx.x & 31;
    int s = __ldg(srcI + e), d = __ldg(dstI + e);
    const float4* Pp = (const float4*)(d_P + (size_t)d*HID);
    const float4* Qp = (const float4*)(d_Q + (size_t)s*HID);
    float* Sp = d_agg + (size_t)d*HID;
#pragma unroll
    for (int j = 0; j < 2; j++) {
        int idx = lane + j*32;
        float4 p = Pp[idx], q = Qp[idx];
        red_add_v4(Sp + idx*4,
                   fmaxf(p.x + q.x, 0.f), fmaxf(p.y + q.y, 0.f),
                   fmaxf(p.z + q.z, 0.f), fmaxf(p.w + q.w, 0.f));
    }
}

// ======== pre-split-A GEMM: [M,256](bf16 hi/lo planes) @ [256,256] ========
// CTA 128x256, BK=32, 256 thr, 8 warps (2M x 4N), 3-stage cp.async pipeline.
// Stage layout: AH 10240 | AL 10240 | BH 20480 | BL 20480 = 61440 B.
// EPI: 2 = acc+bias -> BN(layer) -> relu -> += (hhi+hlo) -> h planes
//      3 = acc -> outp (raw fp32)
//      4 = acc+bias -> outp (fp32)
#define STG_S   61440
#define SMEM_S  (3*STG_S)

template<int EPI>
__global__ __launch_bounds__(256, 1)
void tc_gemm_s(const unsigned short* __restrict__ WH, const unsigned short* __restrict__ WL,
               int ldB,
               const float* __restrict__ bias,
               float* __restrict__ outp,
               const unsigned short* __restrict__ AH, const unsigned short* __restrict__ AL,
               int layer)
{
    extern __shared__ char dynsmem[];
    const uint32_t smem_base = smem_u32(dynsmem);

    const int tid  = threadIdx.x;
    const int lane = tid & 31;
    const int wid  = tid >> 5;
    const int wm   = wid & 1;
    const int wn   = wid >> 1;
    const int g    = lane >> 2;
    const int t4   = lane & 3;
    const int row0 = blockIdx.x * 128;

    // A loader: rows {rta, rta+64}, 16B chunk ca of the 64B row-chunk, both planes
    const int rta = tid >> 2, ca = tid & 3;
    const uint32_t sA0 = (uint32_t)rta*80u + ca*16u;
    const uint32_t sA1 = (uint32_t)(rta + 64)*80u + ca*16u;
    const uint32_t gA0 = (uint32_t)(row0 + rta)*256u + ca*8u;        // halves
    const uint32_t gA1 = (uint32_t)(row0 + rta + 64)*256u + ca*8u;

    // B loader
    const int rtb = tid >> 3, cb = tid & 7;
    uint32_t sBoff[8];
#pragma unroll
    for (int j = 0; j < 8; j++)
        sBoff[j] = (uint32_t)(rtb + j*32)*80u + (uint32_t)(cb & 3)*16u;
    const unsigned short* gB = ((cb < 4) ? WH : WL) + (size_t)rtb*ldB + (cb & 3)*8;
    const uint32_t sBsel = (cb < 4) ? 20480u : 40960u;

    float acc[4][8][4];
#pragma unroll
    for (int mi = 0; mi < 4; mi++)
#pragma unroll
        for (int ni = 0; ni < 8; ni++)
#pragma unroll
            for (int r = 0; r < 4; r++) acc[mi][ni][r] = 0.f;

    const int NC = 8;   // K = 256

    auto load_chunk = [&](int t) {
        const int st = t % 3;
        const int k0 = t*32;
        const uint32_t sa = smem_base + (uint32_t)st*STG_S;
        cp_async16(sa + sA0,          AH + gA0 + k0);
        cp_async16(sa + sA1,          AH + gA1 + k0);
        cp_async16(sa + 10240u + sA0, AL + gA0 + k0);
        cp_async16(sa + 10240u + sA1, AL + gA1 + k0);
        const uint32_t sb = sa + sBsel;
#pragma unroll
        for (int j = 0; j < 8; j++)
            cp_async16(sb + sBoff[j], gB + (size_t)j*32*ldB + k0);
    };

    load_chunk(0); CP_COMMIT();
    load_chunk(1); CP_COMMIT();

    for (int t = 0; t < NC; t++) {
        if (t + 1 < NC) CP_WAIT1(); else CP_WAIT0();
        __syncthreads();
        if (t + 2 < NC) { load_chunk(t + 2); CP_COMMIT(); }

        const char* stg = dynsmem + (t % 3)*STG_S;
        const char* sAH = stg;
        const char* sAL = stg + 10240;
        const char* sBH = stg + 20480;
        const char* sBL = stg + 40960;
#pragma unroll
        for (int ks = 0; ks < 2; ks++) {
            const uint32_t koff = (uint32_t)(ks*32 + t4*4);
            uint32_t ahi[4][4], alo[4][4];
#pragma unroll
            for (int mi = 0; mi < 4; mi++) {
                const uint32_t ro = (uint32_t)(wm*64 + mi*16 + g)*80u + koff;
                ahi[mi][0] = *(const uint32_t*)(sAH + ro);
                ahi[mi][1] = *(const uint32_t*)(sAH + ro + 8*80);
                ahi[mi][2] = *(const uint32_t*)(sAH + ro + 16);
                ahi[mi][3] = *(const uint32_t*)(sAH + ro + 8*80 + 16);
                alo[mi][0] = *(const uint32_t*)(sAL + ro);
                alo[mi][1] = *(const uint32_t*)(sAL + ro + 8*80);
                alo[mi][2] = *(const uint32_t*)(sAL + ro + 16);
                alo[mi][3] = *(const uint32_t*)(sAL + ro + 8*80 + 16);
            }
#pragma unroll
            for (int ni = 0; ni < 8; ni++) {
                const uint32_t boff = (uint32_t)(wn*64 + ni*8 + g)*80u + koff;
                uint32_t bhi[2] = { *(const uint32_t*)(sBH + boff),
                                    *(const uint32_t*)(sBH + boff + 16) };
                uint32_t blo[2] = { *(const uint32_t*)(sBL + boff),
                                    *(const uint32_t*)(sBL + boff + 16) };
#pragma unroll
                for (int mi = 0; mi < 4; mi++) {
                    mma_bf16(acc[mi][ni], ahi[mi], bhi);
                    mma_bf16(acc[mi][ni], ahi[mi], blo);
                    mma_bf16(acc[mi][ni], alo[mi], bhi);
                }
            }
        }
        __syncthreads();
    }

    // ---- epilogue ----
    const int colb = wn*64 + t4*2;
    float2 bias2[8];
    if constexpr (EPI != 3) {
#pragma unroll
        for (int ni = 0; ni < 8; ni++)
            bias2[ni] = *(const float2*)(bias + colb + ni*8);
    }
    float2 sc2[8], sh2[8];
    if constexpr (EPI == 2) {
#pragma unroll
        for (int ni = 0; ni < 8; ni++) {
            sc2[ni] = *(const float2*)(d_bnscale + layer*HID + colb + ni*8);
            sh2[ni] = *(const float2*)(d_bnshift + layer*HID + colb + ni*8);
        }
    }

#pragma unroll
    for (int mi = 0; mi < 4; mi++) {
#pragma unroll
        for (int rh = 0; rh < 2; rh++) {
            const int row = row0 + wm*64 + mi*16 + g + rh*8;
            if constexpr (EPI == 3) {
                float* op = outp + (size_t)row*HID + colb;
#pragma unroll
                for (int ni = 0; ni < 8; ni++)
                    *(float2*)(op + ni*8) = make_float2(acc[mi][ni][rh*2+0],
                                                        acc[mi][ni][rh*2+1]);
            } else if constexpr (EPI == 4) {
                float* op = outp + (size_t)row*HID + colb;
#pragma unroll
                for (int ni = 0; ni < 8; ni++)
                    *(float2*)(op + ni*8) = make_float2(acc[mi][ni][rh*2+0] + bias2[ni].x,
                                                        acc[mi][ni][rh*2+1] + bias2[ni].y);
            } else { // EPI == 2: BN + relu + residual(h planes) -> h planes
                const size_t po = (size_t)row*HID + colb;
#pragma unroll
                for (int ni = 0; ni < 8; ni++) {
                    uint32_t rhv = *(const uint32_t*)(d_hhi + po + ni*8);
                    uint32_t rlv = *(const uint32_t*)(d_hlo + po + ni*8);
                    float2 res = join_bf16x2(rhv, rlv);
                    float u0 = fmaf(acc[mi][ni][rh*2+0] + bias2[ni].x, sc2[ni].x, sh2[ni].x);
                    float u1 = fmaf(acc[mi][ni][rh*2+1] + bias2[ni].y, sc2[ni].y, sh2[ni].y);
                    float o0 = fmaxf(u0, 0.f) + res.x;
                    float o1 = fmaxf(u1, 0.f) + res.y;
                    uint32_t whi, wlo;
                    split_bf16x2(make_float2(o0, o1), whi, wlo);
                    *(uint32_t*)(d_hhi + po + ni*8) = whi;
                    *(uint32_t*)(d_hlo + po + ni*8) = wlo;
                }
            }
        }
    }
}

// ======== fp32-A GEMM (split in mainloop), 2-stage — used where A is fp32 ====
// EPI: 3 = raw fp32 out   6 = relu(t2raw + invdeg*acc + bias + b2f*cvec) -> t2 planes
#define AROWSTR  40
#define BROWSTR  40
#define A_BYTES  (128*AROWSTR*4)
#define BH_BYTES (256*BROWSTR*2)
#define STG_F    (A_BYTES + 2*BH_BYTES)
#define SMEM_F   (2*STG_F)

template<int EPI>
__global__ __launch_bounds__(256, 1)
void tc_gemm_f(const unsigned short* __restrict__ WH, const unsigned short* __restrict__ WL,
               int ldB,
               const float* __restrict__ bias,
               float* __restrict__ outp,
               const float* __restrict__ Ain,
               const float* __restrict__ Ain2,
               const float* __restrict__ cvec,
               int K, int layer)
{
    extern __shared__ char dynsmem[];
    const uint32_t smem_base = smem_u32(dynsmem);

    const int tid  = threadIdx.x;
    const int lane = tid & 31;
    const int wid  = tid >> 5;
    const int wm   = wid & 1;
    const int wn   = wid >> 1;
    const int g    = lane >> 2;
    const int t4   = lane & 3;
    const int row0 = blockIdx.x * 128;

    const int rt = tid >> 3;
    const int cc = tid & 7;
    uint32_t sAoff[4], sBoff[8];
#pragma unroll
    for (int j = 0; j < 4; j++)
        sAoff[j] = (uint32_t)(rt + j*32)*(AROWSTR*4u) + (uint32_t)cc*16u;
#pragma unroll
    for (int j = 0; j < 8; j++)
        sBoff[j] = (uint32_t)(rt + j*32)*(BROWSTR*2u) + (uint32_t)(cc & 3)*16u;

    uint32_t aofs[4];
#pragma unroll
    for (int j = 0; j < 4; j++)
        aofs[j] = (uint32_t)(row0 + rt + j*32)*HID + cc*4u;

    const unsigned short* gB = ((cc < 4) ? WH : WL) + (size_t)rt*ldB + (cc & 3)*8;
    const uint32_t sBsel = (cc < 4) ? 0u : BH_BYTES;

    float acc[4][8][4];
#pragma unroll
    for (int mi = 0; mi < 4; mi++)
#pragma unroll
        for (int ni = 0; ni < 8; ni++)
#pragma unroll
            for (int r = 0; r < 4; r++) acc[mi][ni][r] = 0.f;

    const int NC = K >> 5;

    auto load_chunk = [&](int t, int stage) {
        const int k0 = t*32;
        uint32_t sa  = smem_base + (uint32_t)stage*STG_F;
        uint32_t sbh = sa + A_BYTES + sBsel;
#pragma unroll
        for (int j = 0; j < 4; j++)
            cp_async16(sa + sAoff[j], Ain + aofs[j] + k0);
#pragma unroll
        for (int j = 0; j < 8; j++)
            cp_async16(sbh + sBoff[j], gB + (size_t)j*32*ldB + k0);
    };

    load_chunk(0, 0);
    CP_COMMIT();

    for (int t = 0; t < NC; t++) {
        if (t + 1 < NC) { load_chunk(t + 1, (t + 1) & 1); CP_COMMIT(); CP_WAIT1(); }
        else            { CP_WAIT0(); }
        __syncthreads();

        const char*  stg = dynsmem + (t & 1)*STG_F;
        const float* sA  = (const float*)stg;
        const char*  sBH = stg + A_BYTES;
        const char*  sBL = sBH + BH_BYTES;
#pragma unroll
        for (int ks = 0; ks < 2; ks++) {
            const int kf = ks*16 + t4*2;
            uint32_t ahi[4][4], alo[4][4];
#pragma unroll
            for (int mi = 0; mi < 4; mi++) {
                const float* ap = sA + (wm*64 + mi*16 + g)*AROWSTR + kf;
                float2 v00 = *(const float2*)ap;
                float2 v10 = *(const float2*)(ap + 8*AROWSTR);
                float2 v01 = *(const float2*)(ap + 8);
                float2 v11 = *(const float2*)(ap + 8*AROWSTR + 8);
                split_bf16x2(v00, ahi[mi][0], alo[mi][0]);
                split_bf16x2(v10, ahi[mi][1], alo[mi][1]);
                split_bf16x2(v01, ahi[mi][2], alo[mi][2]);
                split_bf16x2(v11, ahi[mi][3], alo[mi][3]);
            }
#pragma unroll
            for (int ni = 0; ni < 8; ni++) {
                const uint32_t boff = (uint32_t)(wn*64 + ni*8 + g)*(BROWSTR*2u)
                                    + (uint32_t)(ks*16 + t4*2)*2u;
                uint32_t bhi[2] = { *(const uint32_t*)(sBH + boff),
                                    *(const uint32_t*)(sBH + boff + 16) };
                uint32_t blo[2] = { *(const uint32_t*)(sBL + boff),
                                    *(const uint32_t*)(sBL + boff + 16) };
#pragma unroll
                for (int mi = 0; mi < 4; mi++) {
                    mma_bf16(acc[mi][ni], ahi[mi], bhi);
                    mma_bf16(acc[mi][ni], ahi[mi], blo);
                    mma_bf16(acc[mi][ni], alo[mi], bhi);
                }
            }
        }
        __syncthreads();
    }

    const int colb = wn*64 + t4*2;
    float2 bias2[8];
    if constexpr (EPI != 3) {
#pragma unroll
        for (int ni = 0; ni < 8; ni++)
            bias2[ni] = *(const float2*)(bias + colb + ni*8);
    }
    float2 cv2[8];
    if constexpr (EPI == 6) {
#pragma unroll
        for (int ni = 0; ni < 8; ni++)
            cv2[ni] = *(const float2*)(cvec + colb + ni*8);
    }

#pragma unroll
    for (int mi = 0; mi < 4; mi++) {
#pragma unroll
        for (int rh = 0; rh < 2; rh++) {
            const int row = row0 + wm*64 + mi*16 + g + rh*8;
            if constexpr (EPI == 3) {
                float* op = outp + (size_t)row*HID + colb;
#pragma unroll
                for (int ni = 0; ni < 8; ni++)
                    *(float2*)(op + ni*8) = make_float2(acc[mi][ni][rh*2+0],
                                                        acc[mi][ni][rh*2+1]);
            } else { // EPI == 6 -> t2 planes
                const float iv = __ldg(d_invdeg + row);
                const float bf = __ldg(d_b2f + row);
                const float* tp = Ain2 + (size_t)row*HID + colb;
                const size_t po = (size_t)row*HID + colb;
#pragma unroll
                for (int ni = 0; ni < 8; ni++) {
                    float2 tv = *(const float2*)(tp + ni*8);
                    float u0 = tv.x + iv*acc[mi][ni][rh*2+0] + bias2[ni].x + bf*cv2[ni].x;
                    float u1 = tv.y + iv*acc[mi][ni][rh*2+1] + bias2[ni].y + bf*cv2[ni].y;
                    uint32_t whi, wlo;
                    split_bf16x2(make_float2(fmaxf(u0, 0.f), fmaxf(u1, 0.f)), whi, wlo);
                    *(uint32_t*)(d_t2hi + po + ni*8) = whi;
                    *(uint32_t*)(d_t2lo + po + ni*8) = wlo;
                }
            }
        }
    }
}

// out[row] = relu(R[u]+S[v]) . w2 + b2   (R has mlp_b1 folded in)
__global__ void final_pair_dot_kernel(const float* __restrict__ w2,
                                      const float* __restrict__ b2,
                                      float* __restrict__ out) {
    int row  = blockIdx.x*8 + (threadIdx.x >> 5);
    int lane = threadIdx.x & 31;
    int gg = row / 80, bb = row % 80;
    const float* R = d_P + (size_t)(gg*NPG + (bb % 57))*HID;
    const float* S = d_Q + (size_t)(gg*NPG + ((bb*13 + 1) % 57))*HID;
    float s = 0.f;
#pragma unroll
    for (int k = lane; k < HID; k += 32) {
        float v = fmaxf(R[k] + S[k], 0.f);
        s = fmaf(v, __ldg(w2 + k), s);
    }
#pragma unroll
    for (int o = 16; o > 0; o >>= 1) s += __shfl_down_sync(0xffffffffu, s, o);
    if (lane == 0) out[row] = s + b2[0];
}

// ---------------- launch ----------------
extern "C" void kernel_launch(void* const* d_in, const int* in_sizes, int n_in,
                              void* d_out, int out_size)
{
    const float* x      = (const float*)d_in[0];
    const int*   ei     = (const int*)  d_in[1];
    const float* in_w   = (const float*)d_in[3];
    const float* in_b   = (const float*)d_in[4];
    const float* msg_w1 = (const float*)d_in[5];
    const float* msg_b1 = (const float*)d_in[6];
    const float* msg_w2 = (const float*)d_in[7];
    const float* msg_b2 = (const float*)d_in[8];
    const float* upd_w1 = (const float*)d_in[9];
    const float* upd_b1 = (const float*)d_in[10];
    const float* upd_w2 = (const float*)d_in[11];
    const float* upd_b2 = (const float*)d_in[12];
    const float* bn_g   = (const float*)d_in[13];
    const float* bn_b   = (const float*)d_in[14];
    const float* bn_m   = (const float*)d_in[15];
    const float* bn_v   = (const float*)d_in[16];
    const float* mlp_w1 = (const float*)d_in[17];
    const float* mlp_b1 = (const float*)d_in[18];
    const float* mlp_w2 = (const float*)d_in[19];
    const float* mlp_b2 = (const float*)d_in[20];
    float* out = (float*)d_out;

    const int* srcI = ei;
    const int* dstI = ei + NEDGES;

    cudaFuncSetAttribute(tc_gemm_s<2>, cudaFuncAttributeMaxDynamicSharedMemorySize, SMEM_S);
    cudaFuncSetAttribute(tc_gemm_s<3>, cudaFuncAttributeMaxDynamicSharedMemorySize, SMEM_S);
    cudaFuncSetAttribute(tc_gemm_s<4>, cudaFuncAttributeMaxDynamicSharedMemorySize, SMEM_S);
    cudaFuncSetAttribute(tc_gemm_f<3>, cudaFuncAttributeMaxDynamicSharedMemorySize, SMEM_F);
    cudaFuncSetAttribute(tc_gemm_f<6>, cudaFuncAttributeMaxDynamicSharedMemorySize, SMEM_F);

    float *pP, *pQ, *pT2, *pAgg, *pWcf, *pCv;
    cudaGetSymbolAddress((void**)&pP,   d_P);
    cudaGetSymbolAddress((void**)&pQ,   d_Q);
    cudaGetSymbolAddress((void**)&pT2,  d_t2);
    cudaGetSymbolAddress((void**)&pAgg, d_agg);
    cudaGetSymbolAddress((void**)&pWcf, d_wcf);
    cudaGetSymbolAddress((void**)&pCv,  d_cvec);
    unsigned short *pHhi, *pHlo, *pT2hi, *pT2lo;
    cudaGetSymbolAddress((void**)&pHhi,  d_hhi);
    cudaGetSymbolAddress((void**)&pHlo,  d_hlo);
    cudaGetSymbolAddress((void**)&pT2hi, d_t2hi);
    cudaGetSymbolAddress((void**)&pT2lo, d_t2lo);
    unsigned short *pHm1,*pLm1,*pHu1,*pLu1,*pHu2,*pLu2,*pHc,*pLc,*pHr,*pLr;
    cudaGetSymbolAddress((void**)&pHm1, d_bhi_m1); cudaGetSymbolAddress((void**)&pLm1, d_blo_m1);
    cudaGetSymbolAddress((void**)&pHu1, d_bhi_u1); cudaGetSymbolAddress((void**)&pLu1, d_blo_u1);
    cudaGetSymbolAddress((void**)&pHu2, d_bhi_u2); cudaGetSymbolAddress((void**)&pLu2, d_blo_u2);
    cudaGetSymbolAddress((void**)&pHc,  d_bhi_c ); cudaGetSymbolAddress((void**)&pLc,  d_blo_c );
    cudaGetSymbolAddress((void**)&pHr,  d_bhi_r ); cudaGetSymbolAddress((void**)&pLr,  d_blo_r );

    // prep
    deg_zero_kernel <<<(NNODES+255)/256, 256>>>();
    deg_count_kernel<<<(NEDGES+255)/256, 256>>>(dstI);
    deg_inv_kernel  <<<(NNODES+255)/256, 256>>>();
    bn_prep_kernel  <<<(NLAY*HID+255)/256, 256>>>(bn_g, bn_b, bn_m, bn_v);
    input_gemm_kernel<<<NNODES, 256>>>(x, in_w, in_b);

    dim3 tb(32, 8);
    for (int l = 0; l < NLAY; l++) {
        transpose_split_kernel<0><<<dim3(16, 8), tb>>>(msg_w1 + (size_t)l*512*HID, l, 512);
        transpose_split_kernel<2><<<dim3(16, 8), tb>>>(upd_w1 + (size_t)l*512*HID, l, 512);
        transpose_split_kernel<3><<<dim3(8,  8), tb>>>(upd_w2 + (size_t)l*HID*HID, l, 256);
    }
    transpose_split_kernel<4><<<dim3(16, 8), tb>>>(mlp_w1, 0, 512);

    // C_l = msg_w2 @ U1bot, split; cvec_l = msg_b2 @ U1bot
    for (int l = 0; l < NLAY; l++) {
        const size_t o1 = (size_t)l*256*512;
        tc_gemm_f<3><<<2, 256, SMEM_F>>>(pHu1 + o1 + 256, pLu1 + o1 + 256, 512,
            nullptr, pWcf, msg_w2 + (size_t)l*HID*HID, nullptr, nullptr, 256, l);
        transpose_split_kernel<5><<<dim3(8, 8), tb>>>(pWcf, l, 256);
        cvec_kernel<<<1, 256>>>(msg_b2 + l*HID, upd_w1 + (size_t)l*512*HID, pCv + l*HID);
    }

    const int NGRID = NNODES/128;   // 912

    for (int l = 0; l < NLAY; l++) {
        const size_t o1 = (size_t)l*256*512;
        const size_t o2 = (size_t)l*256*256;
        zero_agg_kernel<<<2048, 256>>>();
        // P = h @ W1top + b1   |   Q = h @ W1bot
        tc_gemm_s<4><<<NGRID, 256, SMEM_S>>>(pHm1 + o1, pLm1 + o1, 512,
            msg_b1 + l*HID, pP, pHhi, pHlo, l);
        tc_gemm_s<3><<<NGRID, 256, SMEM_S>>>(pHm1 + o1 + 256, pLm1 + o1 + 256, 512,
            nullptr, pQ, pHhi, pHlo, l);
        // S[dst] += relu(P[dst] + Q[src])
        edge_scatter_kernel<<<NEDGES/8, 256>>>(srcI, dstI);
        // t2raw = h @ U1top
        tc_gemm_s<3><<<NGRID, 256, SMEM_S>>>(pHu1 + o1, pLu1 + o1, 512,
            nullptr, pT2, pHhi, pHlo, l);
        // t2' = relu(t2raw + invdeg*(S@C_l) + upd_b1 + b2f*cvec) -> t2 planes
        tc_gemm_f<6><<<NGRID, 256, SMEM_F>>>(pHc + o2, pLc + o2, 256,
            upd_b1 + l*HID, nullptr, pAgg, pT2, pCv + l*HID, 256, l);
        // h = relu(BN(t2' @ U2 + b2u)) + h   (h planes in/out)
        tc_gemm_s<2><<<NGRID, 256, SMEM_S>>>(pHu2 + o2, pLu2 + o2, 256,
            upd_b2 + l*HID, nullptr, pT2hi, pT2lo, l);
    }

    // readout: R = h@mlpW1top + b1 ; S = h@mlpW1bot ; out = relu(R[u]+S[v]).w2 + b2
    tc_gemm_s<4><<<NGRID, 256, SMEM_S>>>(pHr, pLr, 512,
        mlp_b1, pP, pHhi, pHlo, 0);
    tc_gemm_s<3><<<NGRID, 256, SMEM_S>>>(pHr + 256, pLr + 256, 512,
        nullptr, pQ, pHhi, pHlo, 0);
    final_pair_dot_kernel<<<NEF/8, 256>>>(mlp_w2, mlp_b2, out);
}

// round 10
// speedup vs baseline: 1.9914x; 1.9914x over previous
#include <cuda_runtime.h>
#include <cuda_bf16.h>
#include <cstdint>

#define GNUM   2048
#define NPG    57
#define NNODES (GNUM*NPG)      // 116736
#define EPG    160
#define NEDGES (GNUM*EPG)      // 327680
#define HID    256
#define NLAY   5
#define NEF    (GNUM*80)       // 163840

// ---------------- scratch (static __device__ arrays; no allocs) ----------------
__device__ float d_h   [(size_t)NNODES*HID];
__device__ float d_t2  [(size_t)NNODES*HID];
__device__ float d_agg [(size_t)NNODES*HID];   // S accumulator
__device__ float d_P   [(size_t)NNODES*HID];
__device__ float d_Q   [(size_t)NNODES*HID];
__device__ float d_invdeg [NNODES];
__device__ float d_b2f    [NNODES];
__device__ float d_bnscale[NLAY*HID];
__device__ float d_bnshift[NLAY*HID];
__device__ float d_wcf [(size_t)256*256];
__device__ float d_cvec[(size_t)NLAY*HID];
__device__ float d_zeros[HID];                 // stays zero (.bss)
// transposed, bf16-split weights: [256 out, K] K-major, hi + lo
__device__ unsigned short d_bhi_m1[(size_t)NLAY*256*512];
__device__ unsigned short d_blo_m1[(size_t)NLAY*256*512];
__device__ unsigned short d_bhi_u1[(size_t)NLAY*256*512];
__device__ unsigned short d_blo_u1[(size_t)NLAY*256*512];
__device__ unsigned short d_bhi_u2[(size_t)NLAY*256*256];
__device__ unsigned short d_blo_u2[(size_t)NLAY*256*256];
__device__ unsigned short d_bhi_c [(size_t)NLAY*256*256];
__device__ unsigned short d_blo_c [(size_t)NLAY*256*256];
__device__ unsigned short d_bhi_r [(size_t)256*512];
__device__ unsigned short d_blo_r [(size_t)256*512];

// ---------------- PTX helpers ----------------
__device__ __forceinline__ uint32_t smem_u32(const void* p) {
    uint32_t a;
    asm("{ .reg .u64 t; cvta.to.shared.u64 t, %1; cvt.u32.u64 %0, t; }" : "=r"(a) : "l"(p));
    return a;
}
__device__ __forceinline__ void cp_async16(uint32_t smem, const void* g) {
    asm volatile("cp.async.cg.shared.global [%0], [%1], 16;" :: "r"(smem), "l"(g) : "memory");
}
#define CP_COMMIT() asm volatile("cp.async.commit_group;" ::: "memory")
#define CP_WAIT1()  asm volatile("cp.async.wait_group 1;" ::: "memory")
#define CP_WAIT0()  asm volatile("cp.async.wait_group 0;" ::: "memory")

__device__ __forceinline__ void mma_bf16(float* d, const uint32_t* a, const uint32_t* b) {
    asm volatile(
        "mma.sync.aligned.m16n8k16.row.col.f32.bf16.bf16.f32 "
        "{%0,%1,%2,%3}, {%4,%5,%6,%7}, {%8,%9}, {%0,%1,%2,%3};"
        : "+f"(d[0]), "+f"(d[1]), "+f"(d[2]), "+f"(d[3])
        : "r"(a[0]), "r"(a[1]), "r"(a[2]), "r"(a[3]), "r"(b[0]), "r"(b[1]));
}
__device__ __forceinline__ void red_add_v4(float* p, float a, float b, float c, float d) {
    asm volatile("red.global.add.v4.f32 [%0], {%1, %2, %3, %4};"
                 :: "l"(p), "f"(a), "f"(b), "f"(c), "f"(d) : "memory");
}
__device__ __forceinline__ void split_bf16x2(float2 v, uint32_t& hi, uint32_t& lo) {
    asm("cvt.rn.bf16x2.f32 %0, %1, %2;" : "=r"(hi) : "f"(v.y), "f"(v.x));
    float hlo = __uint_as_float(hi << 16);
    float hhi = __uint_as_float(hi & 0xFFFF0000u);
    asm("cvt.rn.bf16x2.f32 %0, %1, %2;" : "=r"(lo) : "f"(v.y - hhi), "f"(v.x - hlo));
}

// ---------------- small helper kernels ----------------
__global__ void zero_agg_kernel() {
    size_t n4 = (size_t)NNODES*HID/4;
    float4 z = make_float4(0.f,0.f,0.f,0.f);
    for (size_t i = (size_t)blockIdx.x*blockDim.x + threadIdx.x; i < n4;
         i += (size_t)gridDim.x*blockDim.x)
        ((float4*)d_agg)[i] = z;
}
__global__ void scale_agg_kernel() {
    size_t n4 = (size_t)NNODES*HID/4;
    for (size_t i = (size_t)blockIdx.x*blockDim.x + threadIdx.x; i < n4;
         i += (size_t)gridDim.x*blockDim.x) {
        int row = (int)(i >> 6);
        float s = d_invdeg[row];
        float4 v = ((float4*)d_agg)[i];
        v.x*=s; v.y*=s; v.z*=s; v.w*=s;
        ((float4*)d_agg)[i] = v;
    }
}
__global__ void deg_zero_kernel() {
    int i = blockIdx.x*blockDim.x + threadIdx.x;
    if (i < NNODES) d_invdeg[i] = 0.f;
}
__global__ void deg_count_kernel(const int* __restrict__ dst) {
    int e = blockIdx.x*blockDim.x + threadIdx.x;
    if (e < NEDGES) atomicAdd(&d_invdeg[dst[e]], 1.f);
}
__global__ void deg_inv_kernel() {
    int i = blockIdx.x*blockDim.x + threadIdx.x;
    if (i < NNODES) {
        float c = d_invdeg[i];
        d_invdeg[i] = 1.f / fmaxf(c, 1.f);
        d_b2f[i] = (c > 0.f) ? 1.f : 0.f;
    }
}
__global__ void bn_prep_kernel(const float* __restrict__ g, const float* __restrict__ b,
                               const float* __restrict__ m, const float* __restrict__ v) {
    int i = blockIdx.x*blockDim.x + threadIdx.x;
    if (i < NLAY*HID) {
        float sc = g[i] * rsqrtf(v[i] + 1e-5f);
        d_bnscale[i] = sc;
        d_bnshift[i] = b[i] - m[i]*sc;
    }
}
__global__ void input_gemm_kernel(const float* __restrict__ x,
                                  const float* __restrict__ w,
                                  const float* __restrict__ b) {
    int n = blockIdx.x;
    int c = threadIdx.x;
    __shared__ float xs[16];
    if (c < 16) xs[c] = x[n*16 + c];
    __syncthreads();
    float acc = b[c];
#pragma unroll
    for (int k = 0; k < 16; k++) acc = fmaf(xs[k], w[k*HID + c], acc);
    d_h[(size_t)n*HID + c] = acc;
}
__global__ void cvec_kernel(const float* __restrict__ b2,
                            const float* __restrict__ u1,
                            float* __restrict__ outc) {
    int n = threadIdx.x;
    float s = 0.f;
    for (int k = 0; k < 256; k++)
        s = fmaf(b2[k], u1[(size_t)(256 + k)*256 + n], s);
    outc[n] = s;
}
// W [K,256] row-major -> hi/lo bf16 [256,K] row-major
template<int DSEL>
__global__ void transpose_split_kernel(const float* __restrict__ W, int layer, int K) {
    __shared__ float tile[32][33];
    unsigned short *WH, *WL;
    if      constexpr (DSEL == 0) { WH = d_bhi_m1 + (size_t)layer*256*512; WL = d_blo_m1 + (size_t)layer*256*512; }
    else if constexpr (DSEL == 2) { WH = d_bhi_u1 + (size_t)layer*256*512; WL = d_blo_u1 + (size_t)layer*256*512; }
    else if constexpr (DSEL == 3) { WH = d_bhi_u2 + (size_t)layer*256*256; WL = d_blo_u2 + (size_t)layer*256*256; }
    else if constexpr (DSEL == 5) { WH = d_bhi_c  + (size_t)layer*256*256; WL = d_blo_c  + (size_t)layer*256*256; }
    else                          { WH = d_bhi_r; WL = d_blo_r; }
    int kb = blockIdx.x*32, nb = blockIdx.y*32;
    for (int r = threadIdx.y; r < 32; r += 8)
        tile[r][threadIdx.x] = W[(size_t)(kb + r)*256 + nb + threadIdx.x];
    __syncthreads();
    for (int r = threadIdx.y; r < 32; r += 8) {
        float v = tile[threadIdx.x][r];
        __nv_bfloat16 hb = __float2bfloat16(v);
        __nv_bfloat16 lb = __float2bfloat16(v - __bfloat162float(hb));
        size_t o = (size_t)(nb + r)*K + kb + threadIdx.x;
        WH[o] = __bfloat16_as_ushort(hb);
        WL[o] = __bfloat16_as_ushort(lb);
    }
}

// edge scatter: S[dst] += relu(P[dst] + Q[src])
__global__ __launch_bounds__(256, 8)
void edge_scatter_kernel(const int* __restrict__ srcI, const int* __restrict__ dstI) {
    int e    = blockIdx.x*8 + (threadIdx.x >> 5);
    int lane = threadIdx.x & 31;
    int s = __ldg(srcI + e), d = __ldg(dstI + e);
    const float4* Pp = (const float4*)(d_P + (size_t)d*HID);
    const float4* Qp = (const float4*)(d_Q + (size_t)s*HID);
    float* Sp = d_agg + (size_t)d*HID;
#pragma unroll
    for (int j = 0; j < 2; j++) {
        int idx = lane + j*32;
        float4 p = Pp[idx], q = Qp[idx];
        red_add_v4(Sp + idx*4,
                   fmaxf(p.x + q.x, 0.f), fmaxf(p.y + q.y, 0.f),
                   fmaxf(p.z + q.z, 0.f), fmaxf(p.w + q.w, 0.f));
    }
}

// ---------------- bf16x3 split mma.sync GEMM ----------------
// CTA 128x256, BK=32, 256 thr, 8 warps (2M x 4N), 2-stage cp.async.
// CONCAT: A/B second k-half (k>=256) from Ain2 / WH2 (K=512).
// DUAL: grid is two halves; sel picks (bias,out) pair and B k-offset +256.
// EPI: 2 = acc+bias -> BN(layer) -> relu -> += d_h -> d_h
//      3 = acc -> out (raw)
//      4 = acc+bias -> out
//      7 = relu(acc + bias + b2f[row]*cvec) -> out
#define AROWSTR  40
#define BROWSTR  40
#define A_BYTES  (128*AROWSTR*4)
#define BH_BYTES (256*BROWSTR*2)
#define STG_F    (A_BYTES + 2*BH_BYTES)
#define SMEM_F   (2*STG_F)

template<int CONCAT, int DUAL, int EPI>
__global__ __launch_bounds__(256, 1)
void tc_gemm(const unsigned short* __restrict__ WH1, const unsigned short* __restrict__ WL1,
             int ldB1,
             const unsigned short* __restrict__ WH2, const unsigned short* __restrict__ WL2,
             int ldB2,
             const float* __restrict__ bias,  float* __restrict__ outp,
             const float* __restrict__ biasB, float* __restrict__ outpB,
             const float* __restrict__ Ain,  const float* __restrict__ Ain2,
             const float* __restrict__ cvec,
             int K, int layer)
{
    extern __shared__ char dynsmem[];
    const uint32_t smem_base = smem_u32(dynsmem);

    const int tid  = threadIdx.x;
    const int lane = tid & 31;
    const int wid  = tid >> 5;
    const int wm   = wid & 1;
    const int wn   = wid >> 1;
    const int g    = lane >> 2;
    const int t4   = lane & 3;

    int bx = blockIdx.x, sel = 0;
    if constexpr (DUAL) {
        const int halfGrid = gridDim.x >> 1;
        sel = bx >= halfGrid;
        bx -= sel * halfGrid;
    }
    const int row0 = bx * 128;
    const int koffB = DUAL ? sel*256 : 0;

    const int rt = tid >> 3;
    const int cc = tid & 7;
    uint32_t sAoff[4], sBoff[8];
#pragma unroll
    for (int j = 0; j < 4; j++)
        sAoff[j] = (uint32_t)(rt + j*32)*(AROWSTR*4u) + (uint32_t)cc*16u;
#pragma unroll
    for (int j = 0; j < 8; j++)
        sBoff[j] = (uint32_t)(rt + j*32)*(BROWSTR*2u) + (uint32_t)(cc & 3)*16u;

    uint32_t aofs[4];
#pragma unroll
    for (int j = 0; j < 4; j++)
        aofs[j] = (uint32_t)(row0 + rt + j*32)*HID + cc*4u;

    const unsigned short* gB1 = ((cc < 4) ? WH1 : WL1) + (size_t)rt*ldB1 + (cc & 3)*8 + koffB;
    const unsigned short* gB2 = nullptr;
    if constexpr (CONCAT)
        gB2 = ((cc < 4) ? WH2 : WL2) + (size_t)rt*ldB2 + (cc & 3)*8;
    const uint32_t sBsel = (cc < 4) ? 0u : BH_BYTES;

    float acc[4][8][4];
#pragma unroll
    for (int mi = 0; mi < 4; mi++)
#pragma unroll
        for (int ni = 0; ni < 8; ni++)
#pragma unroll
            for (int r = 0; r < 4; r++) acc[mi][ni][r] = 0.f;

    const int NC = K >> 5;

    auto load_chunk = [&](int t, int stage) {
        const int k0 = t*32;
        uint32_t sa  = smem_base + (uint32_t)stage*STG_F;
        uint32_t sbh = sa + A_BYTES + sBsel;
        if (CONCAT && k0 >= 256) {
            const int kin = k0 - 256;
#pragma unroll
            for (int j = 0; j < 4; j++)
                cp_async16(sa + sAoff[j], Ain2 + aofs[j] + kin);
#pragma unroll
            for (int j = 0; j < 8; j++)
                cp_async16(sbh + sBoff[j], gB2 + (size_t)j*32*ldB2 + kin);
        } else {
#pragma unroll
            for (int j = 0; j < 4; j++)
                cp_async16(sa + sAoff[j], Ain + aofs[j] + k0);
#pragma unroll
            for (int j = 0; j < 8; j++)
                cp_async16(sbh + sBoff[j], gB1 + (size_t)j*32*ldB1 + k0);
        }
    };

    load_chunk(0, 0);
    CP_COMMIT();

    for (int t = 0; t < NC; t++) {
        if (t + 1 < NC) { load_chunk(t + 1, (t + 1) & 1); CP_COMMIT(); CP_WAIT1(); }
        else            { CP_WAIT0(); }
        __syncthreads();

        const char*  stg = dynsmem + (t & 1)*STG_F;
        const float* sA  = (const float*)stg;
        const char*  sBH = stg + A_BYTES;
        const char*  sBL = sBH + BH_BYTES;
#pragma unroll
        for (int ks = 0; ks < 2; ks++) {
            const int kf = ks*16 + t4*2;
            uint32_t ahi[4][4], alo[4][4];
#pragma unroll
            for (int mi = 0; mi < 4; mi++) {
                const float* ap = sA + (wm*64 + mi*16 + g)*AROWSTR + kf;
                float2 v00 = *(const float2*)ap;
                float2 v10 = *(const float2*)(ap + 8*AROWSTR);
                float2 v01 = *(const float2*)(ap + 8);
                float2 v11 = *(const float2*)(ap + 8*AROWSTR + 8);
                split_bf16x2(v00, ahi[mi][0], alo[mi][0]);
                split_bf16x2(v10, ahi[mi][1], alo[mi][1]);
                split_bf16x2(v01, ahi[mi][2], alo[mi][2]);
                split_bf16x2(v11, ahi[mi][3], alo[mi][3]);
            }
#pragma unroll
            for (int ni = 0; ni < 8; ni++) {
                const uint32_t boff = (uint32_t)(wn*64 + ni*8 + g)*(BROWSTR*2u)
                                    + (uint32_t)(ks*16 + t4*2)*2u;
                uint32_t bhi[2] = { *(const uint32_t*)(sBH + boff),
                                    *(const uint32_t*)(sBH + boff + 16) };
                uint32_t blo[2] = { *(const uint32_t*)(sBL + boff),
                                    *(const uint32_t*)(sBL + boff + 16) };
#pragma unroll
                for (int mi = 0; mi < 4; mi++) {
                    mma_bf16(acc[mi][ni], ahi[mi], bhi);
                    mma_bf16(acc[mi][ni], ahi[mi], blo);
                    mma_bf16(acc[mi][ni], alo[mi], bhi);
                }
            }
        }
        __syncthreads();
    }

    // ---- epilogue (acc rows g + rh*8, cols t4*2 + ni*8) ----
    const float* biasSel = bias;
    float*       outSel  = outp;
    if constexpr (DUAL) {
        biasSel = sel ? biasB : bias;
        outSel  = sel ? outpB : outp;
    }
    const int colb = wn*64 + t4*2;
    float2 bias2[8];
    if constexpr (EPI != 3) {
#pragma unroll
        for (int ni = 0; ni < 8; ni++)
            bias2[ni] = *(const float2*)(biasSel + colb + ni*8);
    }
    float2 sc2[8], sh2[8];
    if constexpr (EPI == 2) {
#pragma unroll
        for (int ni = 0; ni < 8; ni++) {
            sc2[ni] = *(const float2*)(d_bnscale + layer*HID + colb + ni*8);
            sh2[ni] = *(const float2*)(d_bnshift + layer*HID + colb + ni*8);
        }
    }
    float2 cv2[8];
    if constexpr (EPI == 7) {
#pragma unroll
        for (int ni = 0; ni < 8; ni++)
            cv2[ni] = *(const float2*)(cvec + colb + ni*8);
    }

#pragma unroll
    for (int mi = 0; mi < 4; mi++) {
#pragma unroll
        for (int rh = 0; rh < 2; rh++) {
            const int row = row0 + wm*64 + mi*16 + g + rh*8;
            if constexpr (EPI == 3) {
                float* op = outSel + (size_t)row*HID + colb;
#pragma unroll
                for (int ni = 0; ni < 8; ni++)
                    *(float2*)(op + ni*8) = make_float2(acc[mi][ni][rh*2+0],
                                                        acc[mi][ni][rh*2+1]);
            } else if constexpr (EPI == 4) {
                float* op = outSel + (size_t)row*HID + colb;
#pragma unroll
                for (int ni = 0; ni < 8; ni++)
                    *(float2*)(op + ni*8) = make_float2(acc[mi][ni][rh*2+0] + bias2[ni].x,
                                                        acc[mi][ni][rh*2+1] + bias2[ni].y);
            } else if constexpr (EPI == 7) {
                const float bf = __ldg(d_b2f + row);
                float* op = outSel + (size_t)row*HID + colb;
#pragma unroll
                for (int ni = 0; ni < 8; ni++) {
                    float u0 = acc[mi][ni][rh*2+0] + bias2[ni].x + bf*cv2[ni].x;
                    float u1 = acc[mi][ni][rh*2+1] + bias2[ni].y + bf*cv2[ni].y;
                    *(float2*)(op + ni*8) = make_float2(fmaxf(u0, 0.f), fmaxf(u1, 0.f));
                }
            } else { // EPI == 2
                float* hp = d_h + (size_t)row*HID + colb;
#pragma unroll
                for (int ni = 0; ni < 8; ni++) {
                    float2 res = *(float2*)(hp + ni*8);
                    float u0 = fmaf(acc[mi][ni][rh*2+0] + bias2[ni].x, sc2[ni].x, sh2[ni].x);
                    float u1 = fmaf(acc[mi][ni][rh*2+1] + bias2[ni].y, sc2[ni].y, sh2[ni].y);
                    *(float2*)(hp + ni*8) = make_float2(fmaxf(u0,0.f) + res.x,
                                                        fmaxf(u1,0.f) + res.y);
                }
            }
        }
    }
}

// out[row] = relu(R[u]+S[v]) . w2 + b2   (R has mlp_b1 folded in)
__global__ void final_pair_dot_kernel(const float* __restrict__ w2,
                                      const float* __restrict__ b2,
                                      float* __restrict__ out) {
    int row  = blockIdx.x*8 + (threadIdx.x >> 5);
    int lane = threadIdx.x & 31;
    int gg = row / 80, bb = row % 80;
    const float* R = d_P + (size_t)(gg*NPG + (bb % 57))*HID;
    const float* S = d_Q + (size_t)(gg*NPG + ((bb*13 + 1) % 57))*HID;
    float s = 0.f;
#pragma unroll
    for (int k = lane; k < HID; k += 32) {
        float v = fmaxf(R[k] + S[k], 0.f);
        s = fmaf(v, __ldg(w2 + k), s);
    }
#pragma unroll
    for (int o = 16; o > 0; o >>= 1) s += __shfl_down_sync(0xffffffffu, s, o);
    if (lane == 0) out[row] = s + b2[0];
}

// ---------------- launch ----------------
extern "C" void kernel_launch(void* const* d_in, const int* in_sizes, int n_in,
                              void* d_out, int out_size)
{
    const float* x      = (const float*)d_in[0];
    const int*   ei     = (const int*)  d_in[1];
    const float* in_w   = (const float*)d_in[3];
    const float* in_b   = (const float*)d_in[4];
    const float* msg_w1 = (const float*)d_in[5];
    const float* msg_b1 = (const float*)d_in[6];
    const float* msg_w2 = (const float*)d_in[7];
    const float* msg_b2 = (const float*)d_in[8];
    const float* upd_w1 = (const float*)d_in[9];
    const float* upd_b1 = (const float*)d_in[10];
    const float* upd_w2 = (const float*)d_in[11];
    const float* upd_b2 = (const float*)d_in[12];
    const float* bn_g   = (const float*)d_in[13];
    const float* bn_b   = (const float*)d_in[14];
    const float* bn_m   = (const float*)d_in[15];
    const float* bn_v   = (const float*)d_in[16];
    const float* mlp_w1 = (const float*)d_in[17];
    const float* mlp_b1 = (const float*)d_in[18];
    const float* mlp_w2 = (const float*)d_in[19];
    const float* mlp_b2 = (const float*)d_in[20];
    float* out = (float*)d_out;

    const int* srcI = ei;
    const int* dstI = ei + NEDGES;

    cudaFuncSetAttribute(tc_gemm<0,1,4>, cudaFuncAttributeMaxDynamicSharedMemorySize, SMEM_F);
    cudaFuncSetAttribute(tc_gemm<1,0,7>, cudaFuncAttributeMaxDynamicSharedMemorySize, SMEM_F);
    cudaFuncSetAttribute(tc_gemm<0,0,2>, cudaFuncAttributeMaxDynamicSharedMemorySize, SMEM_F);
    cudaFuncSetAttribute(tc_gemm<0,0,3>, cudaFuncAttributeMaxDynamicSharedMemorySize, SMEM_F);

    float *pP, *pQ, *pT2, *pAgg, *pWcf, *pCv, *pH, *pZero;
    cudaGetSymbolAddress((void**)&pP,    d_P);
    cudaGetSymbolAddress((void**)&pQ,    d_Q);
    cudaGetSymbolAddress((void**)&pT2,   d_t2);
    cudaGetSymbolAddress((void**)&pAgg,  d_agg);
    cudaGetSymbolAddress((void**)&pWcf,  d_wcf);
    cudaGetSymbolAddress((void**)&pCv,   d_cvec);
    cudaGetSymbolAddress((void**)&pH,    d_h);
    cudaGetSymbolAddress((void**)&pZero, d_zeros);
    unsigned short *pHm1,*pLm1,*pHu1,*pLu1,*pHu2,*pLu2,*pHc,*pLc,*pHr,*pLr;
    cudaGetSymbolAddress((void**)&pHm1, d_bhi_m1); cudaGetSymbolAddress((void**)&pLm1, d_blo_m1);
    cudaGetSymbolAddress((void**)&pHu1, d_bhi_u1); cudaGetSymbolAddress((void**)&pLu1, d_blo_u1);
    cudaGetSymbolAddress((void**)&pHu2, d_bhi_u2); cudaGetSymbolAddress((void**)&pLu2, d_blo_u2);
    cudaGetSymbolAddress((void**)&pHc,  d_bhi_c ); cudaGetSymbolAddress((void**)&pLc,  d_blo_c );
    cudaGetSymbolAddress((void**)&pHr,  d_bhi_r ); cudaGetSymbolAddress((void**)&pLr,  d_blo_r );

    // prep
    deg_zero_kernel <<<(NNODES+255)/256, 256>>>();
    deg_count_kernel<<<(NEDGES+255)/256, 256>>>(dstI);
    deg_inv_kernel  <<<(NNODES+255)/256, 256>>>();
    bn_prep_kernel  <<<(NLAY*HID+255)/256, 256>>>(bn_g, bn_b, bn_m, bn_v);
    input_gemm_kernel<<<NNODES, 256>>>(x, in_w, in_b);

    dim3 tb(32, 8);
    for (int l = 0; l < NLAY; l++) {
        transpose_split_kernel<0><<<dim3(16, 8), tb>>>(msg_w1 + (size_t)l*512*HID, l, 512);
        transpose_split_kernel<2><<<dim3(16, 8), tb>>>(upd_w1 + (size_t)l*512*HID, l, 512);
        transpose_split_kernel<3><<<dim3(8,  8), tb>>>(upd_w2 + (size_t)l*HID*HID, l, 256);
    }
    transpose_split_kernel<4><<<dim3(16, 8), tb>>>(mlp_w1, 0, 512);

    // C_l = msg_w2 @ U1bot (fp32 staging), split; cvec_l = msg_b2 @ U1bot
    for (int l = 0; l < NLAY; l++) {
        const size_t o1 = (size_t)l*256*512;
        tc_gemm<0,0,3><<<2, 256, SMEM_F>>>(pHu1 + o1 + 256, pLu1 + o1 + 256, 512,
            nullptr, nullptr, 0,
            nullptr, pWcf, nullptr, nullptr,
            msg_w2 + (size_t)l*HID*HID, nullptr, nullptr, 256, l);
        transpose_split_kernel<5><<<dim3(8, 8), tb>>>(pWcf, l, 256);
        cvec_kernel<<<1, 256>>>(msg_b2 + l*HID, upd_w1 + (size_t)l*512*HID, pCv + l*HID);
    }

    const int NGRID = NNODES/128;   // 912

    for (int l = 0; l < NLAY; l++) {
        const size_t o1 = (size_t)l*256*512;
        const size_t o2 = (size_t)l*256*256;
        zero_agg_kernel<<<2048, 256>>>();
        // fused: P = h@W1top + b1 (first half of grid) | Q = h@W1bot (second half)
        tc_gemm<0,1,4><<<2*NGRID, 256, SMEM_F>>>(pHm1 + o1, pLm1 + o1, 512,
            nullptr, nullptr, 0,
            msg_b1 + l*HID, pP, pZero, pQ,
            pH, nullptr, nullptr, 256, l);
        // S[dst] += relu(P[dst] + Q[src])
        edge_scatter_kernel<<<NEDGES/8, 256>>>(srcI, dstI);
        // S *= invdeg (mean)
        scale_agg_kernel<<<2048, 256>>>();
        // t2 = relu([h | S] @ [U1top ; C_l] + upd_b1 + b2f*cvec)   (K=512 concat)
        tc_gemm<1,0,7><<<NGRID, 256, SMEM_F>>>(pHu1 + o1, pLu1 + o1, 512,
            pHc + o2, pLc + o2, 256,
            upd_b1 + l*HID, pT2, nullptr, nullptr,
            pH, pAgg, pCv + l*HID, 512, l);
        // h = relu(BN(t2 @ U2 + b2u)) + h
        tc_gemm<0,0,2><<<NGRID, 256, SMEM_F>>>(pHu2 + o2, pLu2 + o2, 256,
            nullptr, nullptr, 0,
            upd_b2 + l*HID, nullptr, nullptr, nullptr,
            pT2, nullptr, nullptr, 256, l);
    }

    // readout fused: R = h@mlpW1top + b1 -> P | S = h@mlpW1bot -> Q
    tc_gemm<0,1,4><<<2*NGRID, 256, SMEM_F>>>(pHr, pLr, 512,
        nullptr, nullptr, 0,
        mlp_b1, pP, pZero, pQ,
        pH, nullptr, nullptr, 256, 0);
    final_pair_dot_kernel<<<NEF/8, 256>>>(mlp_w2, mlp_b2, out);
}

// round 11
// speedup vs baseline: 1.9923x; 1.0004x over previous
#include <cuda_runtime.h>
#include <cuda_bf16.h>
#include <cstdint>

#define GNUM   2048
#define NPG    57
#define NNODES (GNUM*NPG)      // 116736
#define EPG    160
#define NEDGES (GNUM*EPG)      // 327680
#define HID    256
#define NLAY   5
#define NEF    (GNUM*80)       // 163840

// ---------------- scratch (static __device__ arrays; no allocs) ----------------
__device__ float d_h   [(size_t)NNODES*HID];
__device__ float d_t2  [(size_t)NNODES*HID];
__device__ float d_agg [(size_t)NNODES*HID];   // S accumulator
__device__ float d_P   [(size_t)NNODES*HID];
__device__ float d_Q   [(size_t)NNODES*HID];
__device__ float d_invdeg [NNODES];
__device__ float d_b2f    [NNODES];
__device__ float d_bnscale[NLAY*HID];
__device__ float d_bnshift[NLAY*HID];
__device__ float d_wcf [(size_t)256*256];
__device__ float d_cvec[(size_t)NLAY*HID];
__device__ float d_zeros[HID];                 // stays zero (.bss)
// transposed, bf16-split weights: [256 out, K] K-major, hi + lo
__device__ unsigned short d_bhi_m1[(size_t)NLAY*256*512];
__device__ unsigned short d_blo_m1[(size_t)NLAY*256*512];
__device__ unsigned short d_bhi_u1[(size_t)NLAY*256*512];
__device__ unsigned short d_blo_u1[(size_t)NLAY*256*512];
__device__ unsigned short d_bhi_u2[(size_t)NLAY*256*256];
__device__ unsigned short d_blo_u2[(size_t)NLAY*256*256];
__device__ unsigned short d_bhi_c [(size_t)NLAY*256*256];
__device__ unsigned short d_blo_c [(size_t)NLAY*256*256];
__device__ unsigned short d_bhi_r [(size_t)256*512];
__device__ unsigned short d_blo_r [(size_t)256*512];

// ---------------- PTX helpers ----------------
__device__ __forceinline__ uint32_t smem_u32(const void* p) {
    uint32_t a;
    asm("{ .reg .u64 t; cvta.to.shared.u64 t, %1; cvt.u32.u64 %0, t; }" : "=r"(a) : "l"(p));
    return a;
}
__device__ __forceinline__ void cp_async16(uint32_t smem, const void* g) {
    asm volatile("cp.async.cg.shared.global [%0], [%1], 16;" :: "r"(smem), "l"(g) : "memory");
}
#define CP_COMMIT() asm volatile("cp.async.commit_group;" ::: "memory")
#define CP_WAIT1()  asm volatile("cp.async.wait_group 1;" ::: "memory")
#define CP_WAIT0()  asm volatile("cp.async.wait_group 0;" ::: "memory")

__device__ __forceinline__ void mma_bf16(float* d, const uint32_t* a, const uint32_t* b) {
    asm volatile(
        "mma.sync.aligned.m16n8k16.row.col.f32.bf16.bf16.f32 "
        "{%0,%1,%2,%3}, {%4,%5,%6,%7}, {%8,%9}, {%0,%1,%2,%3};"
        : "+f"(d[0]), "+f"(d[1]), "+f"(d[2]), "+f"(d[3])
        : "r"(a[0]), "r"(a[1]), "r"(a[2]), "r"(a[3]), "r"(b[0]), "r"(b[1]));
}
__device__ __forceinline__ void red_add_v4(float* p, float a, float b, float c, float d) {
    asm volatile("red.global.add.v4.f32 [%0], {%1, %2, %3, %4};"
                 :: "l"(p), "f"(a), "f"(b), "f"(c), "f"(d) : "memory");
}
__device__ __forceinline__ void split_bf16x2(float2 v, uint32_t& hi, uint32_t& lo) {
    asm("cvt.rn.bf16x2.f32 %0, %1, %2;" : "=r"(hi) : "f"(v.y), "f"(v.x));
    float hlo = __uint_as_float(hi << 16);
    float hhi = __uint_as_float(hi & 0xFFFF0000u);
    asm("cvt.rn.bf16x2.f32 %0, %1, %2;" : "=r"(lo) : "f"(v.y - hhi), "f"(v.x - hlo));
}

// ---------------- small helper kernels ----------------
__global__ void zero_agg_kernel() {
    size_t n4 = (size_t)NNODES*HID/4;
    float4 z = make_float4(0.f,0.f,0.f,0.f);
    for (size_t i = (size_t)blockIdx.x*blockDim.x + threadIdx.x; i < n4;
         i += (size_t)gridDim.x*blockDim.x)
        ((float4*)d_agg)[i] = z;
}
__global__ void scale_agg_kernel() {
    size_t n4 = (size_t)NNODES*HID/4;
    for (size_t i = (size_t)blockIdx.x*blockDim.x + threadIdx.x; i < n4;
         i += (size_t)gridDim.x*blockDim.x) {
        int row = (int)(i >> 6);
        float s = d_invdeg[row];
        float4 v = ((float4*)d_agg)[i];
        v.x*=s; v.y*=s; v.z*=s; v.w*=s;
        ((float4*)d_agg)[i] = v;
    }
}
__global__ void deg_zero_kernel() {
    int i = blockIdx.x*blockDim.x + threadIdx.x;
    if (i < NNODES) d_invdeg[i] = 0.f;
}
__global__ void deg_count_kernel(const int* __restrict__ dst) {
    int e = blockIdx.x*blockDim.x + threadIdx.x;
    if (e < NEDGES) atomicAdd(&d_invdeg[dst[e]], 1.f);
}
__global__ void deg_inv_kernel() {
    int i = blockIdx.x*blockDim.x + threadIdx.x;
    if (i < NNODES) {
        float c = d_invdeg[i];
        d_invdeg[i] = 1.f / fmaxf(c, 1.f);
        d_b2f[i] = (c > 0.f) ? 1.f : 0.f;
    }
}
__global__ void bn_prep_kernel(const float* __restrict__ g, const float* __restrict__ b,
                               const float* __restrict__ m, const float* __restrict__ v) {
    int i = blockIdx.x*blockDim.x + threadIdx.x;
    if (i < NLAY*HID) {
        float sc = g[i] * rsqrtf(v[i] + 1e-5f);
        d_bnscale[i] = sc;
        d_bnshift[i] = b[i] - m[i]*sc;
    }
}
__global__ void input_gemm_kernel(const float* __restrict__ x,
                                  const float* __restrict__ w,
                                  const float* __restrict__ b) {
    int n = blockIdx.x;
    int c = threadIdx.x;
    __shared__ float xs[16];
    if (c < 16) xs[c] = x[n*16 + c];
    __syncthreads();
    float acc = b[c];
#pragma unroll
    for (int k = 0; k < 16; k++) acc = fmaf(xs[k], w[k*HID + c], acc);
    d_h[(size_t)n*HID + c] = acc;
}
__global__ void cvec_kernel(const float* __restrict__ b2,
                            const float* __restrict__ u1,
                            float* __restrict__ outc) {
    int n = threadIdx.x;
    float s = 0.f;
    for (int k = 0; k < 256; k++)
        s = fmaf(b2[k], u1[(size_t)(256 + k)*256 + n], s);
    outc[n] = s;
}
// W [K,256] row-major -> hi/lo bf16 [256,K] row-major
template<int DSEL>
__global__ void transpose_split_kernel(const float* __restrict__ W, int layer, int K) {
    __shared__ float tile[32][33];
    unsigned short *WH, *WL;
    if      constexpr (DSEL == 0) { WH = d_bhi_m1 + (size_t)layer*256*512; WL = d_blo_m1 + (size_t)layer*256*512; }
    else if constexpr (DSEL == 2) { WH = d_bhi_u1 + (size_t)layer*256*512; WL = d_blo_u1 + (size_t)layer*256*512; }
    else if constexpr (DSEL == 3) { WH = d_bhi_u2 + (size_t)layer*256*256; WL = d_blo_u2 + (size_t)layer*256*256; }
    else if constexpr (DSEL == 5) { WH = d_bhi_c  + (size_t)layer*256*256; WL = d_blo_c  + (size_t)layer*256*256; }
    else                          { WH = d_bhi_r; WL = d_blo_r; }
    int kb = blockIdx.x*32, nb = blockIdx.y*32;
    for (int r = threadIdx.y; r < 32; r += 8)
        tile[r][threadIdx.x] = W[(size_t)(kb + r)*256 + nb + threadIdx.x];
    __syncthreads();
    for (int r = threadIdx.y; r < 32; r += 8) {
        float v = tile[threadIdx.x][r];
        __nv_bfloat16 hb = __float2bfloat16(v);
        __nv_bfloat16 lb = __float2bfloat16(v - __bfloat162float(hb));
        size_t o = (size_t)(nb + r)*K + kb + threadIdx.x;
        WH[o] = __bfloat16_as_ushort(hb);
        WL[o] = __bfloat16_as_ushort(lb);
    }
}

// edge scatter: S[dst] += relu(P[dst] + Q[src])
__global__ __launch_bounds__(256, 8)
void edge_scatter_kernel(const int* __restrict__ srcI, const int* __restrict__ dstI) {
    int e    = blockIdx.x*8 + (threadIdx.x >> 5);
    int lane = threadIdx.x & 31;
    int s = __ldg(srcI + e), d = __ldg(dstI + e);
    const float4* Pp = (const float4*)(d_P + (size_t)d*HID);
    const float4* Qp = (const float4*)(d_Q + (size_t)s*HID);
    float* Sp = d_agg + (size_t)d*HID;
#pragma unroll
    for (int j = 0; j < 2; j++) {
        int idx = lane + j*32;
        float4 p = Pp[idx], q = Qp[idx];
        red_add_v4(Sp + idx*4,
                   fmaxf(p.x + q.x, 0.f), fmaxf(p.y + q.y, 0.f),
                   fmaxf(p.z + q.z, 0.f), fmaxf(p.w + q.w, 0.f));
    }
}

// ---------------- bf16x3 split mma.sync GEMM ----------------
// CTA 128x256, BK=32, 256 thr, 8 warps (2M x 4N), 2-stage cp.async.
// R11: term-outermost MMA order — each accumulator re-touched only after 32
// independent MMAs (breaks the 3-deep RAW chains of R6..R10).
// CONCAT: A/B second k-half (k>=256) from Ain2 / WH2 (K=512).
// DUAL: grid is two halves; sel picks (bias,out) pair and B k-offset +256.
// EPI: 2 = acc+bias -> BN(layer) -> relu -> += d_h -> d_h
//      3 = acc -> out (raw)
//      4 = acc+bias -> out
//      7 = relu(acc + bias + b2f[row]*cvec) -> out
#define AROWSTR  40
#define BROWSTR  40
#define A_BYTES  (128*AROWSTR*4)
#define BH_BYTES (256*BROWSTR*2)
#define STG_F    (A_BYTES + 2*BH_BYTES)
#define SMEM_F   (2*STG_F)

template<int CONCAT, int DUAL, int EPI>
__global__ __launch_bounds__(256, 1)
void tc_gemm(const unsigned short* __restrict__ WH1, const unsigned short* __restrict__ WL1,
             int ldB1,
             const unsigned short* __restrict__ WH2, const unsigned short* __restrict__ WL2,
             int ldB2,
             const float* __restrict__ bias,  float* __restrict__ outp,
             const float* __restrict__ biasB, float* __restrict__ outpB,
             const float* __restrict__ Ain,  const float* __restrict__ Ain2,
             const float* __restrict__ cvec,
             int K, int layer)
{
    extern __shared__ char dynsmem[];
    const uint32_t smem_base = smem_u32(dynsmem);

    const int tid  = threadIdx.x;
    const int lane = tid & 31;
    const int wid  = tid >> 5;
    const int wm   = wid & 1;
    const int wn   = wid >> 1;
    const int g    = lane >> 2;
    const int t4   = lane & 3;

    int bx = blockIdx.x, sel = 0;
    if constexpr (DUAL) {
        const int halfGrid = gridDim.x >> 1;
        sel = bx >= halfGrid;
        bx -= sel * halfGrid;
    }
    const int row0 = bx * 128;
    const int koffB = DUAL ? sel*256 : 0;

    const int rt = tid >> 3;
    const int cc = tid & 7;
    uint32_t sAoff[4], sBoff[8];
#pragma unroll
    for (int j = 0; j < 4; j++)
        sAoff[j] = (uint32_t)(rt + j*32)*(AROWSTR*4u) + (uint32_t)cc*16u;
#pragma unroll
    for (int j = 0; j < 8; j++)
        sBoff[j] = (uint32_t)(rt + j*32)*(BROWSTR*2u) + (uint32_t)(cc & 3)*16u;

    uint32_t aofs[4];
#pragma unroll
    for (int j = 0; j < 4; j++)
        aofs[j] = (uint32_t)(row0 + rt + j*32)*HID + cc*4u;

    const unsigned short* gB1 = ((cc < 4) ? WH1 : WL1) + (size_t)rt*ldB1 + (cc & 3)*8 + koffB;
    const unsigned short* gB2 = nullptr;
    if constexpr (CONCAT)
        gB2 = ((cc < 4) ? WH2 : WL2) + (size_t)rt*ldB2 + (cc & 3)*8;
    const uint32_t sBsel = (cc < 4) ? 0u : BH_BYTES;

    float acc[4][8][4];
#pragma unroll
    for (int mi = 0; mi < 4; mi++)
#pragma unroll
        for (int ni = 0; ni < 8; ni++)
#pragma unroll
            for (int r = 0; r < 4; r++) acc[mi][ni][r] = 0.f;

    const int NC = K >> 5;

    auto load_chunk = [&](int t, int stage) {
        const int k0 = t*32;
        uint32_t sa  = smem_base + (uint32_t)stage*STG_F;
        uint32_t sbh = sa + A_BYTES + sBsel;
        if (CONCAT && k0 >= 256) {
            const int kin = k0 - 256;
#pragma unroll
            for (int j = 0; j < 4; j++)
                cp_async16(sa + sAoff[j], Ain2 + aofs[j] + kin);
#pragma unroll
            for (int j = 0; j < 8; j++)
                cp_async16(sbh + sBoff[j], gB2 + (size_t)j*32*ldB2 + kin);
        } else {
#pragma unroll
            for (int j = 0; j < 4; j++)
                cp_async16(sa + sAoff[j], Ain + aofs[j] + k0);
#pragma unroll
            for (int j = 0; j < 8; j++)
                cp_async16(sbh + sBoff[j], gB1 + (size_t)j*32*ldB1 + k0);
        }
    };

    load_chunk(0, 0);
    CP_COMMIT();

    for (int t = 0; t < NC; t++) {
        if (t + 1 < NC) { load_chunk(t + 1, (t + 1) & 1); CP_COMMIT(); CP_WAIT1(); }
        else            { CP_WAIT0(); }
        __syncthreads();

        const char*  stg = dynsmem + (t & 1)*STG_F;
        const float* sA  = (const float*)stg;
        const char*  sBH = stg + A_BYTES;
        const char*  sBL = sBH + BH_BYTES;
#pragma unroll
        for (int ks = 0; ks < 2; ks++) {
            const int kf = ks*16 + t4*2;
            uint32_t ahi[4][4], alo[4][4];
#pragma unroll
            for (int mi = 0; mi < 4; mi++) {
                const float* ap = sA + (wm*64 + mi*16 + g)*AROWSTR + kf;
                float2 v00 = *(const float2*)ap;
                float2 v10 = *(const float2*)(ap + 8*AROWSTR);
                float2 v01 = *(const float2*)(ap + 8);
                float2 v11 = *(const float2*)(ap + 8*AROWSTR + 8);
                split_bf16x2(v00, ahi[mi][0], alo[mi][0]);
                split_bf16x2(v10, ahi[mi][1], alo[mi][1]);
                split_bf16x2(v01, ahi[mi][2], alo[mi][2]);
                split_bf16x2(v11, ahi[mi][3], alo[mi][3]);
            }
            uint32_t bhi[8][2], blo[8][2];
#pragma unroll
            for (int ni = 0; ni < 8; ni++) {
                const uint32_t boff = (uint32_t)(wn*64 + ni*8 + g)*(BROWSTR*2u)
                                    + (uint32_t)(ks*16 + t4*2)*2u;
                bhi[ni][0] = *(const uint32_t*)(sBH + boff);
                bhi[ni][1] = *(const uint32_t*)(sBH + boff + 16);
                blo[ni][0] = *(const uint32_t*)(sBL + boff);
                blo[ni][1] = *(const uint32_t*)(sBL + boff + 16);
            }
            // term 1: Ahi * Bhi — 32 independent accumulators back-to-back
#pragma unroll
            for (int ni = 0; ni < 8; ni++)
#pragma unroll
                for (int mi = 0; mi < 4; mi++)
                    mma_bf16(acc[mi][ni], ahi[mi], bhi[ni]);
            // term 2: Ahi * Blo
#pragma unroll
            for (int ni = 0; ni < 8; ni++)
#pragma unroll
                for (int mi = 0; mi < 4; mi++)
                    mma_bf16(acc[mi][ni], ahi[mi], blo[ni]);
            // term 3: Alo * Bhi
#pragma unroll
            for (int ni = 0; ni < 8; ni++)
#pragma unroll
                for (int mi = 0; mi < 4; mi++)
                    mma_bf16(acc[mi][ni], alo[mi], bhi[ni]);
        }
        __syncthreads();
    }

    // ---- epilogue (acc rows g + rh*8, cols t4*2 + ni*8) ----
    const float* biasSel = bias;
    float*       outSel  = outp;
    if constexpr (DUAL) {
        biasSel = sel ? biasB : bias;
        outSel  = sel ? outpB : outp;
    }
    const int colb = wn*64 + t4*2;
    float2 bias2[8];
    if constexpr (EPI != 3) {
#pragma unroll
        for (int ni = 0; ni < 8; ni++)
            bias2[ni] = *(const float2*)(biasSel + colb + ni*8);
    }
    float2 sc2[8], sh2[8];
    if constexpr (EPI == 2) {
#pragma unroll
        for (int ni = 0; ni < 8; ni++) {
            sc2[ni] = *(const float2*)(d_bnscale + layer*HID + colb + ni*8);
            sh2[ni] = *(const float2*)(d_bnshift + layer*HID + colb + ni*8);
        }
    }
    float2 cv2[8];
    if constexpr (EPI == 7) {
#pragma unroll
        for (int ni = 0; ni < 8; ni++)
            cv2[ni] = *(const float2*)(cvec + colb + ni*8);
    }

#pragma unroll
    for (int mi = 0; mi < 4; mi++) {
#pragma unroll
        for (int rh = 0; rh < 2; rh++) {
            const int row = row0 + wm*64 + mi*16 + g + rh*8;
            if constexpr (EPI == 3) {
                float* op = outSel + (size_t)row*HID + colb;
#pragma unroll
                for (int ni = 0; ni < 8; ni++)
                    *(float2*)(op + ni*8) = make_float2(acc[mi][ni][rh*2+0],
                                                        acc[mi][ni][rh*2+1]);
            } else if constexpr (EPI == 4) {
                float* op = outSel + (size_t)row*HID + colb;
#pragma unroll
                for (int ni = 0; ni < 8; ni++)
                    *(float2*)(op + ni*8) = make_float2(acc[mi][ni][rh*2+0] + bias2[ni].x,
                                                        acc[mi][ni][rh*2+1] + bias2[ni].y);
            } else if constexpr (EPI == 7) {
                const float bf = __ldg(d_b2f + row);
                float* op = outSel + (size_t)row*HID + colb;
#pragma unroll
                for (int ni = 0; ni < 8; ni++) {
                    float u0 = acc[mi][ni][rh*2+0] + bias2[ni].x + bf*cv2[ni].x;
                    float u1 = acc[mi][ni][rh*2+1] + bias2[ni].y + bf*cv2[ni].y;
                    *(float2*)(op + ni*8) = make_float2(fmaxf(u0, 0.f), fmaxf(u1, 0.f));
                }
            } else { // EPI == 2
                float* hp = d_h + (size_t)row*HID + colb;
#pragma unroll
                for (int ni = 0; ni < 8; ni++) {
                    float2 res = *(float2*)(hp + ni*8);
                    float u0 = fmaf(acc[mi][ni][rh*2+0] + bias2[ni].x, sc2[ni].x, sh2[ni].x);
                    float u1 = fmaf(acc[mi][ni][rh*2+1] + bias2[ni].y, sc2[ni].y, sh2[ni].y);
                    *(float2*)(hp + ni*8) = make_float2(fmaxf(u0,0.f) + res.x,
                                                        fmaxf(u1,0.f) + res.y);
                }
            }
        }
    }
}

// out[row] = relu(R[u]+S[v]) . w2 + b2   (R has mlp_b1 folded in)
__global__ void final_pair_dot_kernel(const float* __restrict__ w2,
                                      const float* __restrict__ b2,
                                      float* __restrict__ out) {
    int row  = blockIdx.x*8 + (threadIdx.x >> 5);
    int lane = threadIdx.x & 31;
    int gg = row / 80, bb = row % 80;
    const float* R = d_P + (size_t)(gg*NPG + (bb % 57))*HID;
    const float* S = d_Q + (size_t)(gg*NPG + ((bb*13 + 1) % 57))*HID;
    float s = 0.f;
#pragma unroll
    for (int k = lane; k < HID; k += 32) {
        float v = fmaxf(R[k] + S[k], 0.f);
        s = fmaf(v, __ldg(w2 + k), s);
    }
#pragma unroll
    for (int o = 16; o > 0; o >>= 1) s += __shfl_down_sync(0xffffffffu, s, o);
    if (lane == 0) out[row] = s + b2[0];
}

// ---------------- launch ----------------
extern "C" void kernel_launch(void* const* d_in, const int* in_sizes, int n_in,
                              void* d_out, int out_size)
{
    const float* x      = (const float*)d_in[0];
    const int*   ei     = (const int*)  d_in[1];
    const float* in_w   = (const float*)d_in[3];
    const float* in_b   = (const float*)d_in[4];
    const float* msg_w1 = (const float*)d_in[5];
    const float* msg_b1 = (const float*)d_in[6];
    const float* msg_w2 = (const float*)d_in[7];
    const float* msg_b2 = (const float*)d_in[8];
    const float* upd_w1 = (const float*)d_in[9];
    const float* upd_b1 = (const float*)d_in[10];
    const float* upd_w2 = (const float*)d_in[11];
    const float* upd_b2 = (const float*)d_in[12];
    const float* bn_g   = (const float*)d_in[13];
    const float* bn_b   = (const float*)d_in[14];
    const float* bn_m   = (const float*)d_in[15];
    const float* bn_v   = (const float*)d_in[16];
    const float* mlp_w1 = (const float*)d_in[17];
    const float* mlp_b1 = (const float*)d_in[18];
    const float* mlp_w2 = (const float*)d_in[19];
    const float* mlp_b2 = (const float*)d_in[20];
    float* out = (float*)d_out;

    const int* srcI = ei;
    const int* dstI = ei + NEDGES;

    cudaFuncSetAttribute(tc_gemm<0,1,4>, cudaFuncAttributeMaxDynamicSharedMemorySize, SMEM_F);
    cudaFuncSetAttribute(tc_gemm<1,0,7>, cudaFuncAttributeMaxDynamicSharedMemorySize, SMEM_F);
    cudaFuncSetAttribute(tc_gemm<0,0,2>, cudaFuncAttributeMaxDynamicSharedMemorySize, SMEM_F);
    cudaFuncSetAttribute(tc_gemm<0,0,3>, cudaFuncAttributeMaxDynamicSharedMemorySize, SMEM_F);

    float *pP, *pQ, *pT2, *pAgg, *pWcf, *pCv, *pH, *pZero;
    cudaGetSymbolAddress((void**)&pP,    d_P);
    cudaGetSymbolAddress((void**)&pQ,    d_Q);
    cudaGetSymbolAddress((void**)&pT2,   d_t2);
    cudaGetSymbolAddress((void**)&pAgg,  d_agg);
    cudaGetSymbolAddress((void**)&pWcf,  d_wcf);
    cudaGetSymbolAddress((void**)&pCv,   d_cvec);
    cudaGetSymbolAddress((void**)&pH,    d_h);
    cudaGetSymbolAddress((void**)&pZero, d_zeros);
    unsigned short *pHm1,*pLm1,*pHu1,*pLu1,*pHu2,*pLu2,*pHc,*pLc,*pHr,*pLr;
    cudaGetSymbolAddress((void**)&pHm1, d_bhi_m1); cudaGetSymbolAddress((void**)&pLm1, d_blo_m1);
    cudaGetSymbolAddress((void**)&pHu1, d_bhi_u1); cudaGetSymbolAddress((void**)&pLu1, d_blo_u1);
    cudaGetSymbolAddress((void**)&pHu2, d_bhi_u2); cudaGetSymbolAddress((void**)&pLu2, d_blo_u2);
    cudaGetSymbolAddress((void**)&pHc,  d_bhi_c ); cudaGetSymbolAddress((void**)&pLc,  d_blo_c );
    cudaGetSymbolAddress((void**)&pHr,  d_bhi_r ); cudaGetSymbolAddress((void**)&pLr,  d_blo_r );

    // prep
    deg_zero_kernel <<<(NNODES+255)/256, 256>>>();
    deg_count_kernel<<<(NEDGES+255)/256, 256>>>(dstI);
    deg_inv_kernel  <<<(NNODES+255)/256, 256>>>();
    bn_prep_kernel  <<<(NLAY*HID+255)/256, 256>>>(bn_g, bn_b, bn_m, bn_v);
    input_gemm_kernel<<<NNODES, 256>>>(x, in_w, in_b);

    dim3 tb(32, 8);
    for (int l = 0; l < NLAY; l++) {
        transpose_split_kernel<0><<<dim3(16, 8), tb>>>(msg_w1 + (size_t)l*512*HID, l, 512);
        transpose_split_kernel<2><<<dim3(16, 8), tb>>>(upd_w1 + (size_t)l*512*HID, l, 512);
        transpose_split_kernel<3><<<dim3(8,  8), tb>>>(upd_w2 + (size_t)l*HID*HID, l, 256);
    }
    transpose_split_kernel<4><<<dim3(16, 8), tb>>>(mlp_w1, 0, 512);

    // C_l = msg_w2 @ U1bot (fp32 staging), split; cvec_l = msg_b2 @ U1bot
    for (int l = 0; l < NLAY; l++) {
        const size_t o1 = (size_t)l*256*512;
        tc_gemm<0,0,3><<<2, 256, SMEM_F>>>(pHu1 + o1 + 256, pLu1 + o1 + 256, 512,
            nullptr, nullptr, 0,
            nullptr, pWcf, nullptr, nullptr,
            msg_w2 + (size_t)l*HID*HID, nullptr, nullptr, 256, l);
        transpose_split_kernel<5><<<dim3(8, 8), tb>>>(pWcf, l, 256);
        cvec_kernel<<<1, 256>>>(msg_b2 + l*HID, upd_w1 + (size_t)l*512*HID, pCv + l*HID);
    }

    const int NGRID = NNODES/128;   // 912

    for (int l = 0; l < NLAY; l++) {
        const size_t o1 = (size_t)l*256*512;
        const size_t o2 = (size_t)l*256*256;
        zero_agg_kernel<<<2048, 256>>>();
        // fused: P = h@W1top + b1 (first half of grid) | Q = h@W1bot (second half)
        tc_gemm<0,1,4><<<2*NGRID, 256, SMEM_F>>>(pHm1 + o1, pLm1 + o1, 512,
            nullptr, nullptr, 0,
            msg_b1 + l*HID, pP, pZero, pQ,
            pH, nullptr, nullptr, 256, l);
        // S[dst] += relu(P[dst] + Q[src])
        edge_scatter_kernel<<<NEDGES/8, 256>>>(srcI, dstI);
        // S *= invdeg (mean)
        scale_agg_kernel<<<2048, 256>>>();
        // t2 = relu([h | S] @ [U1top ; C_l] + upd_b1 + b2f*cvec)   (K=512 concat)
        tc_gemm<1,0,7><<<NGRID, 256, SMEM_F>>>(pHu1 + o1, pLu1 + o1, 512,
            pHc + o2, pLc + o2, 256,
            upd_b1 + l*HID, pT2, nullptr, nullptr,
            pH, pAgg, pCv + l*HID, 512, l);
        // h = relu(BN(t2 @ U2 + b2u)) + h
        tc_gemm<0,0,2><<<NGRID, 256, SMEM_F>>>(pHu2 + o2, pLu2 + o2, 256,
            nullptr, nullptr, 0,
            upd_b2 + l*HID, nullptr, nullptr, nullptr,
            pT2, nullptr, nullptr, 256, l);
    }

    // readout fused: R = h@mlpW1top + b1 -> P | S = h@mlpW1bot -> Q
    tc_gemm<0,1,4><<<2*NGRID, 256, SMEM_F>>>(pHr, pLr, 512,
        nullptr, nullptr, 0,
        mlp_b1, pP, pZero, pQ,
        pH, nullptr, nullptr, 256, 0);
    final_pair_dot_kernel<<<NEF/8, 256>>>(mlp_w2, mlp_b2, out);
}